// round 4
// baseline (speedup 1.0000x reference)
#include <cuda_runtime.h>
#include <stdint.h>

// GraphRewiring: transitive closure of body-edge adjacency (attr==0),
// emit shortcut edges (closure & ~adj) appended to original edge list.
//
// R4 (= R3 re-bench + hardening): frontier (delta) expansion — each row
// expands each reachable node exactly ONCE across all passes. 2 warps per
// row (kw-range split), MLP=8 batched L2 gathers. 2 launches total.
//
// Output layout (float32, out_size = 3*(E+N*N)):
//   [0, E)               : edge_index[0] (src) as float
//   [E, E+NN)            : new_src
//   [E+NN, 2E+NN)        : edge_index[1] (dst) as float
//   [2E+NN, 2E+2NN)      : new_dst
//   [2(E+NN), 2(E+NN)+E) : edge_attr copy
//   [2(E+NN)+E, 3(E+NN)) : new_attr (3.0 if shortcut else -1.0)

#define N_NODES 1024
#define NW 32
#define FULLMASK 0xFFFFFFFFu
#define GRID 128
#define TPB 512
#define MAX_ITERS 16
#define NBAR 20

static __device__ uint32_t g_adj[N_NODES * NW];
static __device__ uint32_t g_R[N_NODES * NW];
static __device__ int g_i64flag;
static __device__ int g_bar[NBAR];          // monotone arrival counters
static __device__ int g_changed[MAX_ITERS];

// ---------------------------------------------------------------------------
__global__ void init_kernel(const int* __restrict__ ei32) {
    int t = blockIdx.x * blockDim.x + threadIdx.x;
    if (t < N_NODES * NW) { g_adj[t] = 0u; g_R[t] = 0u; }
    if (t < NBAR) g_bar[t] = 0;
    if (t < MAX_ITERS) g_changed[t] = 0;
    if (t == 0) {
        // int64 little-endian with node ids < 1024 => every odd word is 0.
        int allzero = 1;
        for (int k = 0; k < 64; k++)
            if (ei32[2 * k + 1] != 0) { allzero = 0; break; }
        g_i64flag = allzero;
    }
}

// ---------------------------------------------------------------------------
// Software grid barrier. 128 blocks x 512 threads at 1 block/SM (forced by
// __launch_bounds__(TPB,1)) on 148 SMs => all blocks co-resident, spin is
// deadlock-free. Release fence before arrive; acquire fence after spin.
__device__ __forceinline__ void grid_sync(int slot) {
    __syncthreads();
    if (threadIdx.x == 0) {
        __threadfence();
        atomicAdd(&g_bar[slot], 1);
        while (*(volatile int*)&g_bar[slot] < GRID) __nanosleep(32);
        __threadfence();
    }
    __syncthreads();
}

// ---------------------------------------------------------------------------
__global__ void __launch_bounds__(TPB, 1)
fused_kernel(const int* __restrict__ ei32, const float* __restrict__ attr,
             float* __restrict__ out, int E) {
    const int tid  = blockIdx.x * TPB + threadIdx.x;   // 0..65535
    const int lane = threadIdx.x & 31;
    const int warp = tid >> 5;                         // 0..2047
    const int row  = warp >> 1;                        // 2 warps per row
    const int kwlo = (warp & 1) << 4;                  // kw range [kwlo,kwlo+16)
    const int i64  = g_i64flag;
    const int NN   = N_NODES * N_NODES;
    int bar = 0;

    // ---- Phase 1: copy originals + build body-edge adjacency bitsets ------
    for (int e = tid; e < E; e += GRID * TPB) {
        int src, dst;
        if (i64) { src = ei32[2 * e]; dst = ei32[2 * (E + e)]; }
        else     { src = ei32[e];     dst = ei32[E + e]; }
        float a = attr[e];
        out[e] = (float)src;
        out[(E + NN) + e] = (float)dst;
        out[2 * (E + NN) + e] = a;
        if (a == 0.0f) {
            uint32_t m = 1u << (dst & 31);
            int idx = src * NW + (dst >> 5);
            atomicOr(&g_adj[idx], m);
            atomicOr(&g_R[idx], m);
        }
    }
    grid_sync(bar++);

    // ---- Phase 2: frontier expansion until fixpoint ------------------------
    uint32_t rowreg   = __ldcg(&g_R[row * NW + lane]);
    uint32_t expanded = 0;   // bits already expanded (this warp's kw half used)

    for (int it = 0; it < MAX_ITERS; it++) {
        uint32_t delta = rowreg & ~expanded;
        uint32_t acc = rowreg;
        bool sat = __all_sync(FULLMASK, rowreg == FULLMASK);

        if (!sat && __any_sync(FULLMASK, delta != 0u)) {
            #pragma unroll 1
            for (int kw = kwlo; kw < kwlo + 16; kw++) {
                uint32_t bits = __shfl_sync(FULLMASK, delta, kw);  // warp-uniform
                while (bits) {
                    const int kb = kw << 5;
                    int b = __ffs(bits) - 1; bits &= bits - 1;
                    int k0 = kb + b;
                    int k1 = k0, k2 = k0, k3 = k0, k4 = k0, k5 = k0, k6 = k0, k7 = k0;
                    if (bits) { k1 = kb + __ffs(bits) - 1; bits &= bits - 1; }
                    if (bits) { k2 = kb + __ffs(bits) - 1; bits &= bits - 1; }
                    if (bits) { k3 = kb + __ffs(bits) - 1; bits &= bits - 1; }
                    if (bits) { k4 = kb + __ffs(bits) - 1; bits &= bits - 1; }
                    if (bits) { k5 = kb + __ffs(bits) - 1; bits &= bits - 1; }
                    if (bits) { k6 = kb + __ffs(bits) - 1; bits &= bits - 1; }
                    if (bits) { k7 = kb + __ffs(bits) - 1; bits &= bits - 1; }
                    uint32_t v0 = g_R[(k0 << 5) + lane];
                    uint32_t v1 = g_R[(k1 << 5) + lane];
                    uint32_t v2 = g_R[(k2 << 5) + lane];
                    uint32_t v3 = g_R[(k3 << 5) + lane];
                    uint32_t v4 = g_R[(k4 << 5) + lane];
                    uint32_t v5 = g_R[(k5 << 5) + lane];
                    uint32_t v6 = g_R[(k6 << 5) + lane];
                    uint32_t v7 = g_R[(k7 << 5) + lane];
                    acc |= (v0 | v1) | (v2 | v3) | (v4 | v5) | (v6 | v7);
                    if (__all_sync(FULLMASK, acc == FULLMASK)) { sat = true; goto scan_done; }
                }
            }
        scan_done:;
        }

        expanded = sat ? FULLMASK : rowreg;   // every pre-pass bit now expanded
        uint32_t newbits = acc & ~rowreg;
        if (__any_sync(FULLMASK, newbits != 0u)) {
            if (newbits) atomicOr(&g_R[row * NW + lane], newbits);
            if (lane == 0) g_changed[it] = 1;
        }
        grid_sync(bar++);
        rowreg = __ldcg(&g_R[row * NW + lane]);       // fresh merged row
        if (*(volatile int*)&g_changed[it] == 0) break;  // grid-uniform fixpoint
    }

    // ---- Phase 3: emit shortcut slots (closure & ~adj) ---------------------
    // One 32-bit word (32 edge slots) per thread for tid < 32768.
    if (tid < N_NODES * NW) {
        int t = tid;
        uint32_t sc = __ldcg(&g_R[t]) & ~g_adj[t];
        int p_base = t << 5;
        int j0 = (t & 31) << 5;
        float fi = (float)(t >> 5);

        float* so = out + E + p_base;                   // new_src
        float* dd = out + (E + NN) + E + p_base;        // new_dst
        float* ao = out + 2 * (E + NN) + E + p_base;    // new_attr

        #pragma unroll
        for (int q = 0; q < 32; q += 4) {
            bool b0 = (sc >> (q + 0)) & 1u;
            bool b1 = (sc >> (q + 1)) & 1u;
            bool b2 = (sc >> (q + 2)) & 1u;
            bool b3 = (sc >> (q + 3)) & 1u;
            float4 s4 = make_float4(b0 ? fi : 0.f, b1 ? fi : 0.f,
                                    b2 ? fi : 0.f, b3 ? fi : 0.f);
            float4 d4 = make_float4(b0 ? (float)(j0 + q + 0) : 0.f,
                                    b1 ? (float)(j0 + q + 1) : 0.f,
                                    b2 ? (float)(j0 + q + 2) : 0.f,
                                    b3 ? (float)(j0 + q + 3) : 0.f);
            float4 a4 = make_float4(b0 ? 3.f : -1.f, b1 ? 3.f : -1.f,
                                    b2 ? 3.f : -1.f, b3 ? 3.f : -1.f);
            *(float4*)(so + q) = s4;
            *(float4*)(dd + q) = d4;
            *(float4*)(ao + q) = a4;
        }
    }
}

// ---------------------------------------------------------------------------
extern "C" void kernel_launch(void* const* d_in, const int* in_sizes, int n_in,
                              void* d_out, int out_size) {
    const int* ei = (const int*)d_in[0];
    const float* attr = (const float*)d_in[1];
    float* out = (float*)d_out;
    int E = in_sizes[1];

    init_kernel<<<64, 512>>>(ei);
    fused_kernel<<<GRID, TPB>>>(ei, attr, out, E);
}